// round 13
// baseline (speedup 1.0000x reference)
#include <cuda_runtime.h>
#include <cuda_bf16.h>
#include <cuda_fp16.h>
#include <math.h>
#include <stdint.h>

// Problem dims
#define Bn  2
#define Sn  2048
#define Dn  2048
#define Hn  16
#define DHn 128
#define Mn  (Bn*Sn)   // 4096

typedef __nv_bfloat16 bf16;
typedef __nv_bfloat162 bf162;

// ---------------- scratch (device globals; no allocation allowed) ----------
__device__ __half g_xhi[(size_t)Mn*Dn];
__device__ __half g_xlo[(size_t)Mn*Dn];
__device__ __half g_whi[4][(size_t)Dn*Dn];   // wq, wk, wv, wo  [K,N]
__device__ __half g_wlo[4][(size_t)Dn*Dn];
__device__ bf16 g_Q[(size_t)Bn*Hn*Sn*DHn];   // [b,h,s,dh]
__device__ bf16 g_K[(size_t)Bn*Hn*Sn*DHn];
__device__ bf16 g_V[(size_t)Bn*Hn*Sn*DHn];
__device__ __half g_attnb[(size_t)Mn*Dn];    // [b,s,d] fp16 (exact bf16 values)
__device__ float2 g_rope[(size_t)Sn*64];     // (cos, sin)

__device__ __forceinline__ unsigned saddr(const void* p) {
    return (unsigned)__cvta_generic_to_shared(p);
}

// ---------------- cp.async helpers -----------------------------------------
__device__ __forceinline__ void cpa16(unsigned s, const void* g) {
    asm volatile("cp.async.cg.shared.global [%0], [%1], 16;\n" :: "r"(s), "l"(g));
}
__device__ __forceinline__ void cpcommit() {
    asm volatile("cp.async.commit_group;\n" ::);
}
template<int NW> __device__ __forceinline__ void cpwait() {
    asm volatile("cp.async.wait_group %0;\n" :: "n"(NW));
}

// ---------------- helpers ---------------------------------------------------
__global__ void split_kernel(const float* __restrict__ s,
                             __half* __restrict__ hi, __half* __restrict__ lo, int n4)
{
    int i = blockIdx.x * blockDim.x + threadIdx.x;
    if (i >= n4) return;
    float4 v = reinterpret_cast<const float4*>(s)[i];
    __half h0 = __float2half(v.x), h1 = __float2half(v.y);
    __half h2 = __float2half(v.z), h3 = __float2half(v.w);
    __half2 H0; H0.x = h0; H0.y = h1;
    __half2 H1; H1.x = h2; H1.y = h3;
    reinterpret_cast<__half2*>(hi)[2*i]   = H0;
    reinterpret_cast<__half2*>(hi)[2*i+1] = H1;
    __half2 L0, L1;
    L0.x = __float2half(v.x - __half2float(h0));
    L0.y = __float2half(v.y - __half2float(h1));
    L1.x = __float2half(v.z - __half2float(h2));
    L1.y = __float2half(v.w - __half2float(h3));
    reinterpret_cast<__half2*>(lo)[2*i]   = L0;
    reinterpret_cast<__half2*>(lo)[2*i+1] = L1;
}

// fused 4-weight split: blockIdx.y selects the weight matrix
__global__ void wsplit_all(const float* __restrict__ w0, const float* __restrict__ w1,
                           const float* __restrict__ w2, const float* __restrict__ w3,
                           __half* __restrict__ hiB, __half* __restrict__ loB)
{
    const int which = blockIdx.y;
    const float* s = (which == 0) ? w0 : (which == 1) ? w1 : (which == 2) ? w2 : w3;
    __half* hi = hiB + (size_t)which * Dn * Dn;
    __half* lo = loB + (size_t)which * Dn * Dn;
    int i = blockIdx.x * blockDim.x + threadIdx.x;
    float4 v = reinterpret_cast<const float4*>(s)[i];
    __half h0 = __float2half(v.x), h1 = __float2half(v.y);
    __half h2 = __float2half(v.z), h3 = __float2half(v.w);
    __half2 H0; H0.x = h0; H0.y = h1;
    __half2 H1; H1.x = h2; H1.y = h3;
    reinterpret_cast<__half2*>(hi)[2*i]   = H0;
    reinterpret_cast<__half2*>(hi)[2*i+1] = H1;
    __half2 L0, L1;
    L0.x = __float2half(v.x - __half2float(h0));
    L0.y = __float2half(v.y - __half2float(h1));
    L1.x = __float2half(v.z - __half2float(h2));
    L1.y = __float2half(v.w - __half2float(h3));
    reinterpret_cast<__half2*>(lo)[2*i]   = L0;
    reinterpret_cast<__half2*>(lo)[2*i+1] = L1;
}

__global__ void rope_tab_kernel()
{
    int idx = blockIdx.x * blockDim.x + threadIdx.x;   // s*64 + i
    if (idx >= Sn * 64) return;
    int s = idx >> 6, i = idx & 63;
    const float LOG1E4 = 9.210340371976184f;
    float inv = expf(-((float)(2 * i) / 128.0f) * LOG1E4);
    float ang = (float)s * inv;
    float sn, cs;
    sincosf(ang, &sn, &cs);
    g_rope[idx] = make_float2(cs, sn);
}

// ---------------- mma primitives -------------------------------------------
__device__ __forceinline__ void ldmA(unsigned &r0, unsigned &r1, unsigned &r2, unsigned &r3, unsigned a) {
    asm volatile("ldmatrix.sync.aligned.m8n8.x4.shared.b16 {%0,%1,%2,%3}, [%4];"
                 : "=r"(r0), "=r"(r1), "=r"(r2), "=r"(r3) : "r"(a));
}
__device__ __forceinline__ void ldmBT(unsigned &r0, unsigned &r1, unsigned &r2, unsigned &r3, unsigned a) {
    asm volatile("ldmatrix.sync.aligned.m8n8.x4.trans.shared.b16 {%0,%1,%2,%3}, [%4];"
                 : "=r"(r0), "=r"(r1), "=r"(r2), "=r"(r3) : "r"(a));
}
__device__ __forceinline__ void mma16816(float* d, const unsigned* a, const unsigned* b) {
    asm volatile("mma.sync.aligned.m16n8k16.row.col.f32.f16.f16.f32 "
                 "{%0,%1,%2,%3}, {%4,%5,%6,%7}, {%8,%9}, {%0,%1,%2,%3};"
                 : "+f"(d[0]), "+f"(d[1]), "+f"(d[2]), "+f"(d[3])
                 : "r"(a[0]), "r"(a[1]), "r"(a[2]), "r"(a[3]), "r"(b[0]), "r"(b[1]));
}
__device__ __forceinline__ void mma16816bf(float* d, const unsigned* a, const unsigned* b) {
    asm volatile("mma.sync.aligned.m16n8k16.row.col.f32.bf16.bf16.f32 "
                 "{%0,%1,%2,%3}, {%4,%5,%6,%7}, {%8,%9}, {%0,%1,%2,%3};"
                 : "+f"(d[0]), "+f"(d[1]), "+f"(d[2]), "+f"(d[3])
                 : "r"(a[0]), "r"(a[1]), "r"(a[2]), "r"(a[3]), "r"(b[0]), "r"(b[1]));
}

// ---------------- fp16 tensor-core GEMM: 256 thr, block 128x64, 2 CTAs/SM ---
// 8 warps (4x2), 32x32 warp tiles, k-tile 32, 4-stage cp.async, 1 sync/iter.
// KIND 0 (QKV fused): grid.x = 96: which = bx>>5, n-tile = bx&31; 3 phases.
// KIND 1 (out proj): grid.x = 32; 2 phases; f32 out.
// fp32 drain every 4 iters (HMMA chain length 8 per element — unchanged).
constexpr int LDA = 40, LDB = 72;
constexpr int A_STG = 128 * LDA;     // 128 x 32 tile
constexpr int B_STG = 32 * LDB;      // 32 x 64 tile
constexpr int NSTG  = 4;
constexpr int SMEM_BYTES = NSTG * (A_STG + B_STG) * 2;   // 59,392

template<int KIND>
__global__ void __launch_bounds__(256)
gemm_mma(const __half* __restrict__ a_hi, const __half* __restrict__ a_lo,
         const __half* __restrict__ w_hi, const __half* __restrict__ w_lo,
         float* __restrict__ outF)
{
    constexpr int K = Dn, N = Dn;
    extern __shared__ __half smem[];
    __half* AsBase = smem;
    __half* BsBase = smem + NSTG * A_STG;

    const int tid = threadIdx.x;
    const int wid = tid >> 5, lane = tid & 31;
    const int wm = wid & 3, wn = wid >> 2;       // 4 x 2 warps, 32x32 tiles
    const int m0 = blockIdx.y * 128;

    int mode, n0, nPhase;
    const __half *APh[3], *BPh[3];
    if (KIND == 0) {
        const int which = blockIdx.x >> 5;
        mode = which;
        n0 = (blockIdx.x & 31) * 64;
        const __half* W1 = w_hi + (size_t)which * Dn * Dn;
        const __half* W2 = w_lo + (size_t)which * Dn * Dn;
        APh[0] = a_hi; APh[1] = a_lo; APh[2] = a_hi;
        BPh[0] = W1;   BPh[1] = W1;   BPh[2] = W2;
        nPhase = 3;
    } else {
        mode = 3;
        n0 = blockIdx.x * 64;
        APh[0] = a_hi; APh[1] = a_hi; APh[2] = a_hi;
        BPh[0] = w_hi; BPh[1] = w_lo; BPh[2] = w_lo;
        nPhase = 2;
    }
    const int nIter = nPhase * (K / 32);   // phase = i>>6, ktile = i&63

    float d[2][4][4];     // HMMA accumulator (32x32 warp tile)
    float sum[2][4][4];   // fp32 master accumulator
    #pragma unroll
    for (int mf = 0; mf < 2; mf++)
        #pragma unroll
        for (int nf = 0; nf < 4; nf++)
            #pragma unroll
            for (int e = 0; e < 4; e++) { d[mf][nf][e] = 0.f; sum[mf][nf][e] = 0.f; }

    // loading layout (256 threads): A row tid>>1, 2 chunks at (tid&1)*16;
    // B row tid>>3, chunk (tid&7)*8.
    const int arow = tid >> 1, acol = (tid & 1) * 16;
    const int brow = tid >> 3, bcol = (tid & 7) * 8;

    unsigned sA[NSTG], sB[NSTG];
    #pragma unroll
    for (int b = 0; b < NSTG; b++) {
        sA[b] = saddr(AsBase + b * A_STG + arow * LDA + acol);
        sB[b] = saddr(BsBase + b * B_STG + brow * LDB + bcol);
    }

    auto issue = [&](int i) {
        const int ph = i >> 6;
        const int kt = (i & 63) * 32;
        const __half* ga = APh[ph] + (size_t)(m0 + arow) * K + acol + kt;
        const __half* gb = BPh[ph] + (size_t)(kt + brow) * N + n0 + bcol;
        const int b = i & (NSTG - 1);
        cpa16(sA[b],      ga);
        cpa16(sA[b] + 16, ga + 8);
        cpa16(sB[b],      gb);
        cpcommit();
    };

    issue(0);
    issue(1);
    issue(2);

    for (int i = 0; i < nIter; i++) {
        if (i + 2 < nIter)      cpwait<2>();
        else if (i + 1 < nIter) cpwait<1>();
        else                    cpwait<0>();
        __syncthreads();
        if (i + 3 < nIter) issue(i + 3);

        const int stg = i & (NSTG - 1);
        const __half* as = AsBase + stg * A_STG;
        const __half* bs = BsBase + stg * B_STG;

        #pragma unroll
        for (int kk = 0; kk < 32; kk += 16) {
            unsigned a[2][4];
            #pragma unroll
            for (int mf = 0; mf < 2; mf++) {
                const __half* p = as + (wm * 32 + mf * 16 + (lane & 15)) * LDA
                                     + kk + (lane >> 4) * 8;
                ldmA(a[mf][0], a[mf][1], a[mf][2], a[mf][3], saddr(p));
            }
            unsigned bfr[4][2];
            #pragma unroll
            for (int nq = 0; nq < 2; nq++) {
                const __half* p = bs + (kk + (lane & 15)) * LDB
                                     + wn * 32 + nq * 16 + (lane >> 4) * 8;
                unsigned r0, r1, r2, r3;
                ldmBT(r0, r1, r2, r3, saddr(p));
                bfr[nq*2][0] = r0; bfr[nq*2][1] = r1;
                bfr[nq*2+1][0] = r2; bfr[nq*2+1][1] = r3;
            }
            #pragma unroll
            for (int mf = 0; mf < 2; mf++)
                #pragma unroll
                for (int nf = 0; nf < 4; nf++)
                    mma16816(d[mf][nf], a[mf], bfr[nf]);
        }

        // drain every 4 k-tiles (HMMA chain length 8 per element — unchanged)
        if ((i & 3) == 3) {
            #pragma unroll
            for (int mf = 0; mf < 2; mf++)
                #pragma unroll
                for (int nf = 0; nf < 4; nf++)
                    #pragma unroll
                    for (int e = 0; e < 4; e++) {
                        sum[mf][nf][e] += d[mf][nf][e];
                        d[mf][nf][e] = 0.f;
                    }
        }
    }

    const int lr = lane >> 2;
    const int lc = (lane & 3) * 2;
    #pragma unroll
    for (int mf = 0; mf < 2; mf++) {
        #pragma unroll
        for (int nf = 0; nf < 4; nf++) {
            float* dd = sum[mf][nf];
            const int row0 = m0 + wm * 32 + mf * 16 + lr;
            const int col  = n0 + wn * 32 + nf * 8 + lc;
            #pragma unroll
            for (int half = 0; half < 2; half++) {
                const int row = row0 + half * 8;
                const float e = dd[half*2], o = dd[half*2 + 1];
                if (KIND == 1) {
                    *reinterpret_cast<float2*>(outF + (size_t)row * N + col) =
                        make_float2(e, o);
                } else {
                    const int b = row >> 11, s = row & (Sn - 1);
                    const int h = col >> 7, jd = col & (DHn - 1);
                    bf16* dst = (mode == 0) ? g_Q : (mode == 1) ? g_K : g_V;
                    bf162 val;
                    if (mode == 2) {
                        val.x = __float2bfloat16(e);
                        val.y = __float2bfloat16(o);
                    } else {
                        float2 cssn = g_rope[s * 64 + (jd >> 1)];
                        val.x = __float2bfloat16(e * cssn.x - o * cssn.y);
                        val.y = __float2bfloat16(e * cssn.y + o * cssn.x);
                    }
                    *reinterpret_cast<bf162*>(
                        dst + ((size_t)(b * Hn + h) * Sn + s) * DHn + jd) = val;
                }
            }
        }
    }
}

// ============================================================
// Tensor-core two-pass causal flash attention (R8 config:
// 64 q-rows/CTA, 4 warps, 128 threads).
// ============================================================
constexpr int FLD = 136;
constexpr int FTILE = 64 * FLD;
constexpr int FLASH_SMEM = 3 * FTILE * 2;   // 52,224

__global__ void __launch_bounds__(128)
flash_tc()
{
    extern __shared__ bf16 fs[];
    bf16* Qs = fs;
    bf16* Ks = fs + FTILE;
    bf16* Vs = fs + 2 * FTILE;

    const int tid  = threadIdx.x;
    const int warp = tid >> 5, lane = tid & 31;
    const int bh   = blockIdx.y;
    const int q0   = blockIdx.x * 64;
    const int nT   = blockIdx.x + 1;
    const float scale = 0.08838834764831845f;

    const bf16* Qg = g_Q + ((size_t)bh * Sn + q0) * DHn;
    const bf16* Kg = g_K + (size_t)bh * Sn * DHn;
    const bf16* Vg = g_V + (size_t)bh * Sn * DHn;

    const int lrow = tid & 63;
    const int lcb  = (tid >> 6) << 6;

    auto load_tile = [&](const bf16* g, bf16* s) {
        const bf16* gp = g + (size_t)lrow * DHn + lcb;
        unsigned sp = saddr(s + lrow * FLD + lcb);
        #pragma unroll
        for (int i = 0; i < 8; i++) cpa16(sp + i * 16, gp + i * 8);
    };

    load_tile(Qg, Qs);
    cpcommit();

    const int lr = lane >> 2;
    const int lc = (lane & 3) * 2;
    const int rA = q0 + warp * 16 + lr;
    const int rB = rA + 8;

    auto computeS = [&](float c[8][4], int kt) {
        #pragma unroll
        for (int nf = 0; nf < 8; nf++)
            #pragma unroll
            for (int e = 0; e < 4; e++) c[nf][e] = 0.f;
        #pragma unroll
        for (int ks = 0; ks < 8; ks++) {
            unsigned a[4];
            ldmA(a[0], a[1], a[2], a[3],
                 saddr(Qs + (warp * 16 + (lane & 15)) * FLD + ks * 16 + (lane >> 4) * 8));
            unsigned bk[8][2];
            #pragma unroll
            for (int nq = 0; nq < 4; nq++) {
                unsigned r0, r1, r2, r3;
                ldmA(r0, r1, r2, r3,
                     saddr(Ks + (nq * 16 + (lane & 15)) * FLD + ks * 16 + (lane >> 4) * 8));
                bk[nq*2][0]   = r0; bk[nq*2][1]   = r2;
                bk[nq*2+1][0] = r1; bk[nq*2+1][1] = r3;
            }
            #pragma unroll
            for (int nf = 0; nf < 8; nf++)
                mma16816bf(c[nf], a, bk[nf]);
        }
        if (kt == nT - 1) {
            #pragma unroll
            for (int nf = 0; nf < 8; nf++) {
                const int col = kt * 64 + nf * 8 + lc;
                c[nf][0] = (col     <= rA) ? c[nf][0] * scale : -INFINITY;
                c[nf][1] = (col + 1 <= rA) ? c[nf][1] * scale : -INFINITY;
                c[nf][2] = (col     <= rB) ? c[nf][2] * scale : -INFINITY;
                c[nf][3] = (col + 1 <= rB) ? c[nf][3] * scale : -INFINITY;
            }
        } else {
            #pragma unroll
            for (int nf = 0; nf < 8; nf++)
                #pragma unroll
                for (int e = 0; e < 4; e++) c[nf][e] *= scale;
        }
    };

    float mA = -INFINITY, lA = 0.f, mB = -INFINITY, lB = 0.f;
    for (int kt = 0; kt < nT; kt++) {
        __syncthreads();
        load_tile(Kg + (size_t)kt * 64 * DHn, Ks);
        cpcommit();
        cpwait<0>();
        __syncthreads();

        float c[8][4];
        computeS(c, kt);

        float tA = -INFINITY, tB = -INFINITY;
        #pragma unroll
        for (int nf = 0; nf < 8; nf++) {
            tA = fmaxf(tA, fmaxf(c[nf][0], c[nf][1]));
            tB = fmaxf(tB, fmaxf(c[nf][2], c[nf][3]));
        }
        tA = fmaxf(tA, __shfl_xor_sync(0xffffffffu, tA, 1));
        tA = fmaxf(tA, __shfl_xor_sync(0xffffffffu, tA, 2));
        tB = fmaxf(tB, __shfl_xor_sync(0xffffffffu, tB, 1));
        tB = fmaxf(tB, __shfl_xor_sync(0xffffffffu, tB, 2));

        const float mnA = fmaxf(mA, tA), mnB = fmaxf(mB, tB);
        float sA = 0.f, sB = 0.f;
        #pragma unroll
        for (int nf = 0; nf < 8; nf++) {
            sA += __expf(c[nf][0] - mnA) + __expf(c[nf][1] - mnA);
            sB += __expf(c[nf][2] - mnB) + __expf(c[nf][3] - mnB);
        }
        sA += __shfl_xor_sync(0xffffffffu, sA, 1);
        sA += __shfl_xor_sync(0xffffffffu, sA, 2);
        sB += __shfl_xor_sync(0xffffffffu, sB, 1);
        sB += __shfl_xor_sync(0xffffffffu, sB, 2);

        lA = lA * __expf(mA - mnA) + sA; mA = mnA;
        lB = lB * __expf(mB - mnB) + sB; mB = mnB;
    }
    const float invA = 1.0f / lA, invB = 1.0f / lB;

    float o[16][4];
    #pragma unroll
    for (int nb = 0; nb < 16; nb++)
        #pragma unroll
        for (int e = 0; e < 4; e++) o[nb][e] = 0.f;

    for (int kt = 0; kt < nT; kt++) {
        __syncthreads();
        load_tile(Kg + (size_t)kt * 64 * DHn, Ks);
        load_tile(Vg + (size_t)kt * 64 * DHn, Vs);
        cpcommit();
        cpwait<0>();
        __syncthreads();

        float c[8][4];
        computeS(c, kt);

        unsigned pr[8][2];
        #pragma unroll
        for (int nf = 0; nf < 8; nf++) {
            bf162 v0, v1;
            v0.x = __float2bfloat16(__expf(c[nf][0] - mA) * invA);
            v0.y = __float2bfloat16(__expf(c[nf][1] - mA) * invA);
            v1.x = __float2bfloat16(__expf(c[nf][2] - mB) * invB);
            v1.y = __float2bfloat16(__expf(c[nf][3] - mB) * invB);
            pr[nf][0] = *reinterpret_cast<unsigned*>(&v0);
            pr[nf][1] = *reinterpret_cast<unsigned*>(&v1);
        }

        float d[16][4];
        #pragma unroll
        for (int nb = 0; nb < 16; nb++)
            #pragma unroll
            for (int e = 0; e < 4; e++) d[nb][e] = 0.f;

        #pragma unroll
        for (int kb = 0; kb < 4; kb++) {
            unsigned a[4] = {pr[2*kb][0], pr[2*kb][1], pr[2*kb+1][0], pr[2*kb+1][1]};
            unsigned bv[16][2];
            #pragma unroll
            for (int nbp = 0; nbp < 8; nbp++) {
                unsigned r0, r1, r2, r3;
                ldmBT(r0, r1, r2, r3,
                      saddr(Vs + (kb * 16 + (lane & 15)) * FLD + nbp * 16 + (lane >> 4) * 8));
                bv[nbp*2][0]   = r0; bv[nbp*2][1]   = r1;
                bv[nbp*2+1][0] = r2; bv[nbp*2+1][1] = r3;
            }
            #pragma unroll
            for (int nb = 0; nb < 16; nb++)
                mma16816bf(d[nb], a, bv[nb]);
        }
        #pragma unroll
        for (int nb = 0; nb < 16; nb++)
            #pragma unroll
            for (int e = 0; e < 4; e++) o[nb][e] += d[nb][e];
    }

    const int b = bh >> 4, h = bh & 15;
    #pragma unroll
    for (int nb = 0; nb < 16; nb++) {
        const int col = nb * 8 + lc;
        __half2 vA, vB;
        vA.x = __float2half(__bfloat162float(__float2bfloat16(o[nb][0])));
        vA.y = __float2half(__bfloat162float(__float2bfloat16(o[nb][1])));
        vB.x = __float2half(__bfloat162float(__float2bfloat16(o[nb][2])));
        vB.y = __float2half(__bfloat162float(__float2bfloat16(o[nb][3])));
        *reinterpret_cast<__half2*>(
            g_attnb + ((size_t)(b * Sn + rA)) * Dn + h * DHn + col) = vA;
        *reinterpret_cast<__half2*>(
            g_attnb + ((size_t)(b * Sn + rB)) * Dn + h * DHn + col) = vB;
    }
}

// ============================================================
extern "C" void kernel_launch(void* const* d_in, const int* in_sizes, int n_in,
                              void* d_out, int out_size)
{
    const float* x  = (const float*)d_in[0];
    const float* w[4] = {(const float*)d_in[1], (const float*)d_in[2],
                         (const float*)d_in[3], (const float*)d_in[4]};
    float* out = (float*)d_out;

    __half *xhi, *xlo, *whiB, *wloB, *attnb;
    cudaGetSymbolAddress((void**)&xhi, g_xhi);
    cudaGetSymbolAddress((void**)&xlo, g_xlo);
    cudaGetSymbolAddress((void**)&attnb, g_attnb);
    cudaGetSymbolAddress((void**)&whiB, g_whi);
    cudaGetSymbolAddress((void**)&wloB, g_wlo);

    cudaFuncSetAttribute(gemm_mma<0>, cudaFuncAttributeMaxDynamicSharedMemorySize, SMEM_BYTES);
    cudaFuncSetAttribute(gemm_mma<1>, cudaFuncAttributeMaxDynamicSharedMemorySize, SMEM_BYTES);
    cudaFuncSetAttribute(flash_tc, cudaFuncAttributeMaxDynamicSharedMemorySize, FLASH_SMEM);

    const int n4 = Mn * Dn / 4;
    const int m4 = Dn * Dn / 4;

    rope_tab_kernel<<<(Sn * 64 + 255) / 256, 256>>>();                 // 0
    split_kernel<<<(n4 + 255) / 256, 256>>>(x, xhi, xlo, n4);          // 1
    wsplit_all<<<dim3(m4 / 256, 4), 256>>>(w[0], w[1], w[2], w[3],     // 2
                                           whiB, wloB);

    // 3: fused QKV projection (rope + bf16 epilogues)
    gemm_mma<0><<<dim3(96, Mn / 128), 256, SMEM_BYTES>>>(xhi, xlo, whiB, wloB, nullptr);

    // 4: flash attention
    flash_tc<<<dim3(Sn / 64, Bn * Hn), 128, FLASH_SMEM>>>();

    // 5: out = attnb @ wo (2 phases)
    gemm_mma<1><<<dim3(32, Mn / 128), 256, SMEM_BYTES>>>(
        attnb, nullptr, whiB + (size_t)3 * Dn * Dn, wloB + (size_t)3 * Dn * Dn, out);
}

// round 14
// speedup vs baseline: 1.0047x; 1.0047x over previous
#include <cuda_runtime.h>
#include <cuda_bf16.h>
#include <cuda_fp16.h>
#include <math.h>
#include <stdint.h>

// Problem dims
#define Bn  2
#define Sn  2048
#define Dn  2048
#define Hn  16
#define DHn 128
#define Mn  (Bn*Sn)   // 4096

typedef __nv_bfloat16 bf16;
typedef __nv_bfloat162 bf162;

// ---------------- scratch (device globals; no allocation allowed) ----------
__device__ __half g_xhi[(size_t)Mn*Dn];
__device__ __half g_xlo[(size_t)Mn*Dn];
__device__ __half g_whi[4][(size_t)Dn*Dn];   // wq, wk, wv, wo  [K,N]
__device__ __half g_wlo[4][(size_t)Dn*Dn];
__device__ bf16 g_Q[(size_t)Bn*Hn*Sn*DHn];   // [b,h,s,dh]
__device__ bf16 g_K[(size_t)Bn*Hn*Sn*DHn];
__device__ bf16 g_V[(size_t)Bn*Hn*Sn*DHn];
__device__ __half g_attnb[(size_t)Mn*Dn];    // [b,s,d] fp16 (exact bf16 values)
__device__ float2 g_rope[(size_t)Sn*64];     // (cos, sin)

__device__ __forceinline__ unsigned saddr(const void* p) {
    return (unsigned)__cvta_generic_to_shared(p);
}

// ---------------- cp.async helpers -----------------------------------------
__device__ __forceinline__ void cpa16(unsigned s, const void* g) {
    asm volatile("cp.async.cg.shared.global [%0], [%1], 16;\n" :: "r"(s), "l"(g));
}
__device__ __forceinline__ void cpcommit() {
    asm volatile("cp.async.commit_group;\n" ::);
}
template<int NW> __device__ __forceinline__ void cpwait() {
    asm volatile("cp.async.wait_group %0;\n" :: "n"(NW));
}

// ---------------- helpers ---------------------------------------------------
__global__ void split_kernel(const float* __restrict__ s,
                             __half* __restrict__ hi, __half* __restrict__ lo, int n4)
{
    int i = blockIdx.x * blockDim.x + threadIdx.x;
    if (i >= n4) return;
    float4 v = reinterpret_cast<const float4*>(s)[i];
    __half h0 = __float2half(v.x), h1 = __float2half(v.y);
    __half h2 = __float2half(v.z), h3 = __float2half(v.w);
    __half2 H0; H0.x = h0; H0.y = h1;
    __half2 H1; H1.x = h2; H1.y = h3;
    reinterpret_cast<__half2*>(hi)[2*i]   = H0;
    reinterpret_cast<__half2*>(hi)[2*i+1] = H1;
    __half2 L0, L1;
    L0.x = __float2half(v.x - __half2float(h0));
    L0.y = __float2half(v.y - __half2float(h1));
    L1.x = __float2half(v.z - __half2float(h2));
    L1.y = __float2half(v.w - __half2float(h3));
    reinterpret_cast<__half2*>(lo)[2*i]   = L0;
    reinterpret_cast<__half2*>(lo)[2*i+1] = L1;
}

// fused 4-weight split: blockIdx.y selects the weight matrix
__global__ void wsplit_all(const float* __restrict__ w0, const float* __restrict__ w1,
                           const float* __restrict__ w2, const float* __restrict__ w3,
                           __half* __restrict__ hiB, __half* __restrict__ loB)
{
    const int which = blockIdx.y;
    const float* s = (which == 0) ? w0 : (which == 1) ? w1 : (which == 2) ? w2 : w3;
    __half* hi = hiB + (size_t)which * Dn * Dn;
    __half* lo = loB + (size_t)which * Dn * Dn;
    int i = blockIdx.x * blockDim.x + threadIdx.x;
    float4 v = reinterpret_cast<const float4*>(s)[i];
    __half h0 = __float2half(v.x), h1 = __float2half(v.y);
    __half h2 = __float2half(v.z), h3 = __float2half(v.w);
    __half2 H0; H0.x = h0; H0.y = h1;
    __half2 H1; H1.x = h2; H1.y = h3;
    reinterpret_cast<__half2*>(hi)[2*i]   = H0;
    reinterpret_cast<__half2*>(hi)[2*i+1] = H1;
    __half2 L0, L1;
    L0.x = __float2half(v.x - __half2float(h0));
    L0.y = __float2half(v.y - __half2float(h1));
    L1.x = __float2half(v.z - __half2float(h2));
    L1.y = __float2half(v.w - __half2float(h3));
    reinterpret_cast<__half2*>(lo)[2*i]   = L0;
    reinterpret_cast<__half2*>(lo)[2*i+1] = L1;
}

__global__ void rope_tab_kernel()
{
    int idx = blockIdx.x * blockDim.x + threadIdx.x;   // s*64 + i
    if (idx >= Sn * 64) return;
    int s = idx >> 6, i = idx & 63;
    const float LOG1E4 = 9.210340371976184f;
    float inv = expf(-((float)(2 * i) / 128.0f) * LOG1E4);
    float ang = (float)s * inv;
    float sn, cs;
    sincosf(ang, &sn, &cs);
    g_rope[idx] = make_float2(cs, sn);
}

// ---------------- mma primitives -------------------------------------------
__device__ __forceinline__ void ldmA(unsigned &r0, unsigned &r1, unsigned &r2, unsigned &r3, unsigned a) {
    asm volatile("ldmatrix.sync.aligned.m8n8.x4.shared.b16 {%0,%1,%2,%3}, [%4];"
                 : "=r"(r0), "=r"(r1), "=r"(r2), "=r"(r3) : "r"(a));
}
__device__ __forceinline__ void ldmBT(unsigned &r0, unsigned &r1, unsigned &r2, unsigned &r3, unsigned a) {
    asm volatile("ldmatrix.sync.aligned.m8n8.x4.trans.shared.b16 {%0,%1,%2,%3}, [%4];"
                 : "=r"(r0), "=r"(r1), "=r"(r2), "=r"(r3) : "r"(a));
}
__device__ __forceinline__ void mma16816(float* d, const unsigned* a, const unsigned* b) {
    asm volatile("mma.sync.aligned.m16n8k16.row.col.f32.f16.f16.f32 "
                 "{%0,%1,%2,%3}, {%4,%5,%6,%7}, {%8,%9}, {%0,%1,%2,%3};"
                 : "+f"(d[0]), "+f"(d[1]), "+f"(d[2]), "+f"(d[3])
                 : "r"(a[0]), "r"(a[1]), "r"(a[2]), "r"(a[3]), "r"(b[0]), "r"(b[1]));
}
__device__ __forceinline__ void mma16816bf(float* d, const unsigned* a, const unsigned* b) {
    asm volatile("mma.sync.aligned.m16n8k16.row.col.f32.bf16.bf16.f32 "
                 "{%0,%1,%2,%3}, {%4,%5,%6,%7}, {%8,%9}, {%0,%1,%2,%3};"
                 : "+f"(d[0]), "+f"(d[1]), "+f"(d[2]), "+f"(d[3])
                 : "r"(a[0]), "r"(a[1]), "r"(a[2]), "r"(a[3]), "r"(b[0]), "r"(b[1]));
}

// ---------------- fp16 tensor-core GEMM (exact R12 config) ------------------
// 512 thr, 16 warps (4x4), 32x32 warp tiles, block 128x128, k-tile 32,
// 4-stage cp.async, 1 sync/iter. fp32 drain every 4 iters (chain 8).
constexpr int LDA = 40, LDB = 136;
constexpr int A_STG = 128 * LDA;
constexpr int B_STG = 32 * LDB;
constexpr int NSTG  = 4;
constexpr int SMEM_BYTES = NSTG * (A_STG + B_STG) * 2;   // 75,776

template<int KIND>
__global__ void __launch_bounds__(512)
gemm_mma(const __half* __restrict__ a_hi, const __half* __restrict__ a_lo,
         const __half* __restrict__ w_hi, const __half* __restrict__ w_lo,
         float* __restrict__ outF)
{
    constexpr int K = Dn, N = Dn;
    extern __shared__ __half smem[];
    __half* AsBase = smem;
    __half* BsBase = smem + NSTG * A_STG;

    const int tid = threadIdx.x;
    const int wid = tid >> 5, lane = tid & 31;
    const int wm = wid & 3, wn = wid >> 2;       // 4 x 4 warps, 32x32 tiles
    const int m0 = blockIdx.y * 128;

    int mode, n0, nPhase;
    const __half *APh[3], *BPh[3];
    if (KIND == 0) {
        const int which = blockIdx.x >> 4;
        mode = which;
        n0 = (blockIdx.x & 15) * 128;
        const __half* W1 = w_hi + (size_t)which * Dn * Dn;
        const __half* W2 = w_lo + (size_t)which * Dn * Dn;
        APh[0] = a_hi; APh[1] = a_lo; APh[2] = a_hi;
        BPh[0] = W1;   BPh[1] = W1;   BPh[2] = W2;
        nPhase = 3;
    } else {
        mode = 3;
        n0 = blockIdx.x * 128;
        APh[0] = a_hi; APh[1] = a_hi; APh[2] = a_hi;
        BPh[0] = w_hi; BPh[1] = w_lo; BPh[2] = w_lo;
        nPhase = 2;
    }
    const int nIter = nPhase * (K / 32);

    float d[2][4][4];
    float sum[2][4][4];
    #pragma unroll
    for (int mf = 0; mf < 2; mf++)
        #pragma unroll
        for (int nf = 0; nf < 4; nf++)
            #pragma unroll
            for (int e = 0; e < 4; e++) { d[mf][nf][e] = 0.f; sum[mf][nf][e] = 0.f; }

    const int arow = tid >> 2, acol = (tid & 3) * 8;
    const int brow = tid >> 4, bcol = (tid & 15) * 8;

    unsigned sA[NSTG], sB[NSTG];
    #pragma unroll
    for (int b = 0; b < NSTG; b++) {
        sA[b] = saddr(AsBase + b * A_STG + arow * LDA + acol);
        sB[b] = saddr(BsBase + b * B_STG + brow * LDB + bcol);
    }

    auto issue = [&](int i) {
        const int ph = i >> 6;
        const int kt = (i & 63) * 32;
        const __half* ga = APh[ph] + (size_t)(m0 + arow) * K + acol + kt;
        const __half* gb = BPh[ph] + (size_t)(kt + brow) * N + n0 + bcol;
        const int b = i & (NSTG - 1);
        cpa16(sA[b], ga);
        cpa16(sB[b], gb);
        cpcommit();
    };

    issue(0);
    issue(1);
    issue(2);

    for (int i = 0; i < nIter; i++) {
        if (i + 2 < nIter)      cpwait<2>();
        else if (i + 1 < nIter) cpwait<1>();
        else                    cpwait<0>();
        __syncthreads();
        if (i + 3 < nIter) issue(i + 3);

        const int stg = i & (NSTG - 1);
        const __half* as = AsBase + stg * A_STG;
        const __half* bs = BsBase + stg * B_STG;

        #pragma unroll
        for (int kk = 0; kk < 32; kk += 16) {
            unsigned a[2][4];
            #pragma unroll
            for (int mf = 0; mf < 2; mf++) {
                const __half* p = as + (wm * 32 + mf * 16 + (lane & 15)) * LDA
                                     + kk + (lane >> 4) * 8;
                ldmA(a[mf][0], a[mf][1], a[mf][2], a[mf][3], saddr(p));
            }
            unsigned bfr[4][2];
            #pragma unroll
            for (int nq = 0; nq < 2; nq++) {
                const __half* p = bs + (kk + (lane & 15)) * LDB
                                     + wn * 32 + nq * 16 + (lane >> 4) * 8;
                unsigned r0, r1, r2, r3;
                ldmBT(r0, r1, r2, r3, saddr(p));
                bfr[nq*2][0] = r0; bfr[nq*2][1] = r1;
                bfr[nq*2+1][0] = r2; bfr[nq*2+1][1] = r3;
            }
            #pragma unroll
            for (int mf = 0; mf < 2; mf++)
                #pragma unroll
                for (int nf = 0; nf < 4; nf++)
                    mma16816(d[mf][nf], a[mf], bfr[nf]);
        }

        if ((i & 3) == 3) {
            #pragma unroll
            for (int mf = 0; mf < 2; mf++)
                #pragma unroll
                for (int nf = 0; nf < 4; nf++)
                    #pragma unroll
                    for (int e = 0; e < 4; e++) {
                        sum[mf][nf][e] += d[mf][nf][e];
                        d[mf][nf][e] = 0.f;
                    }
        }
    }

    const int lr = lane >> 2;
    const int lc = (lane & 3) * 2;
    #pragma unroll
    for (int mf = 0; mf < 2; mf++) {
        #pragma unroll
        for (int nf = 0; nf < 4; nf++) {
            float* dd = sum[mf][nf];
            const int row0 = m0 + wm * 32 + mf * 16 + lr;
            const int col  = n0 + wn * 32 + nf * 8 + lc;
            #pragma unroll
            for (int half = 0; half < 2; half++) {
                const int row = row0 + half * 8;
                const float e = dd[half*2], o = dd[half*2 + 1];
                if (KIND == 1) {
                    *reinterpret_cast<float2*>(outF + (size_t)row * N + col) =
                        make_float2(e, o);
                } else {
                    const int b = row >> 11, s = row & (Sn - 1);
                    const int h = col >> 7, jd = col & (DHn - 1);
                    bf16* dst = (mode == 0) ? g_Q : (mode == 1) ? g_K : g_V;
                    bf162 val;
                    if (mode == 2) {
                        val.x = __float2bfloat16(e);
                        val.y = __float2bfloat16(o);
                    } else {
                        float2 cssn = g_rope[s * 64 + (jd >> 1)];
                        val.x = __float2bfloat16(e * cssn.x - o * cssn.y);
                        val.y = __float2bfloat16(e * cssn.y + o * cssn.x);
                    }
                    *reinterpret_cast<bf162*>(
                        dst + ((size_t)(b * Hn + h) * Sn + s) * DHn + jd) = val;
                }
            }
        }
    }
}

// ============================================================
// Tensor-core two-pass causal flash attention, 64 q-rows/CTA,
// with DOUBLE-BUFFERED K/V tile pipeline.
// ============================================================
constexpr int FLD = 136;
constexpr int FTILE = 64 * FLD;
constexpr int FLASH_SMEM = 5 * FTILE * 2;   // Q + 2K + 2V = 87,040

__global__ void __launch_bounds__(128)
flash_tc()
{
    extern __shared__ bf16 fs[];
    bf16* Qs = fs;
    bf16* KsB[2] = {fs + FTILE, fs + 2 * FTILE};
    bf16* VsB[2] = {fs + 3 * FTILE, fs + 4 * FTILE};

    const int tid  = threadIdx.x;
    const int warp = tid >> 5, lane = tid & 31;
    const int bh   = blockIdx.y;
    const int q0   = blockIdx.x * 64;
    const int nT   = blockIdx.x + 1;
    const float scale = 0.08838834764831845f;

    const bf16* Qg = g_Q + ((size_t)bh * Sn + q0) * DHn;
    const bf16* Kg = g_K + (size_t)bh * Sn * DHn;
    const bf16* Vg = g_V + (size_t)bh * Sn * DHn;

    const int lrow = tid & 63;
    const int lcb  = (tid >> 6) << 6;

    auto load_tile = [&](const bf16* g, bf16* s) {
        const bf16* gp = g + (size_t)lrow * DHn + lcb;
        unsigned sp = saddr(s + lrow * FLD + lcb);
        #pragma unroll
        for (int i = 0; i < 8; i++) cpa16(sp + i * 16, gp + i * 8);
    };

    load_tile(Qg, Qs);
    cpcommit();

    const int lr = lane >> 2;
    const int lc = (lane & 3) * 2;
    const int rA = q0 + warp * 16 + lr;
    const int rB = rA + 8;

    auto computeS = [&](float c[8][4], int kt, const bf16* Ks) {
        #pragma unroll
        for (int nf = 0; nf < 8; nf++)
            #pragma unroll
            for (int e = 0; e < 4; e++) c[nf][e] = 0.f;
        #pragma unroll
        for (int ks = 0; ks < 8; ks++) {
            unsigned a[4];
            ldmA(a[0], a[1], a[2], a[3],
                 saddr(Qs + (warp * 16 + (lane & 15)) * FLD + ks * 16 + (lane >> 4) * 8));
            unsigned bk[8][2];
            #pragma unroll
            for (int nq = 0; nq < 4; nq++) {
                unsigned r0, r1, r2, r3;
                ldmA(r0, r1, r2, r3,
                     saddr(Ks + (nq * 16 + (lane & 15)) * FLD + ks * 16 + (lane >> 4) * 8));
                bk[nq*2][0]   = r0; bk[nq*2][1]   = r2;
                bk[nq*2+1][0] = r1; bk[nq*2+1][1] = r3;
            }
            #pragma unroll
            for (int nf = 0; nf < 8; nf++)
                mma16816bf(c[nf], a, bk[nf]);
        }
        if (kt == nT - 1) {
            #pragma unroll
            for (int nf = 0; nf < 8; nf++) {
                const int col = kt * 64 + nf * 8 + lc;
                c[nf][0] = (col     <= rA) ? c[nf][0] * scale : -INFINITY;
                c[nf][1] = (col + 1 <= rA) ? c[nf][1] * scale : -INFINITY;
                c[nf][2] = (col     <= rB) ? c[nf][2] * scale : -INFINITY;
                c[nf][3] = (col + 1 <= rB) ? c[nf][3] * scale : -INFINITY;
            }
        } else {
            #pragma unroll
            for (int nf = 0; nf < 8; nf++)
                #pragma unroll
                for (int e = 0; e < 4; e++) c[nf][e] *= scale;
        }
    };

    // ---- pass 1: m, l (double-buffered K) ----
    float mA = -INFINITY, lA = 0.f, mB = -INFINITY, lB = 0.f;
    load_tile(Kg, KsB[0]);
    cpcommit();
    for (int kt = 0; kt < nT; kt++) {
        __syncthreads();                     // prior compute done; buffer free
        if (kt + 1 < nT) {
            load_tile(Kg + (size_t)(kt + 1) * 64 * DHn, KsB[(kt + 1) & 1]);
            cpcommit();
            cpwait<1>();
        } else {
            cpwait<0>();
        }
        __syncthreads();

        float c[8][4];
        computeS(c, kt, KsB[kt & 1]);

        float tA = -INFINITY, tB = -INFINITY;
        #pragma unroll
        for (int nf = 0; nf < 8; nf++) {
            tA = fmaxf(tA, fmaxf(c[nf][0], c[nf][1]));
            tB = fmaxf(tB, fmaxf(c[nf][2], c[nf][3]));
        }
        tA = fmaxf(tA, __shfl_xor_sync(0xffffffffu, tA, 1));
        tA = fmaxf(tA, __shfl_xor_sync(0xffffffffu, tA, 2));
        tB = fmaxf(tB, __shfl_xor_sync(0xffffffffu, tB, 1));
        tB = fmaxf(tB, __shfl_xor_sync(0xffffffffu, tB, 2));

        const float mnA = fmaxf(mA, tA), mnB = fmaxf(mB, tB);
        float sA = 0.f, sB = 0.f;
        #pragma unroll
        for (int nf = 0; nf < 8; nf++) {
            sA += __expf(c[nf][0] - mnA) + __expf(c[nf][1] - mnA);
            sB += __expf(c[nf][2] - mnB) + __expf(c[nf][3] - mnB);
        }
        sA += __shfl_xor_sync(0xffffffffu, sA, 1);
        sA += __shfl_xor_sync(0xffffffffu, sA, 2);
        sB += __shfl_xor_sync(0xffffffffu, sB, 1);
        sB += __shfl_xor_sync(0xffffffffu, sB, 2);

        lA = lA * __expf(mA - mnA) + sA; mA = mnA;
        lB = lB * __expf(mB - mnB) + sB; mB = mnB;
    }
    const float invA = 1.0f / lA, invB = 1.0f / lB;

    // ---- pass 2: O = bf16(p) V (double-buffered K+V) ----
    float o[16][4];
    #pragma unroll
    for (int nb = 0; nb < 16; nb++)
        #pragma unroll
        for (int e = 0; e < 4; e++) o[nb][e] = 0.f;

    __syncthreads();                         // pass-1 compute fully done
    load_tile(Kg, KsB[0]);
    load_tile(Vg, VsB[0]);
    cpcommit();
    for (int kt = 0; kt < nT; kt++) {
        __syncthreads();
        if (kt + 1 < nT) {
            load_tile(Kg + (size_t)(kt + 1) * 64 * DHn, KsB[(kt + 1) & 1]);
            load_tile(Vg + (size_t)(kt + 1) * 64 * DHn, VsB[(kt + 1) & 1]);
            cpcommit();
            cpwait<1>();
        } else {
            cpwait<0>();
        }
        __syncthreads();

        const bf16* Ks = KsB[kt & 1];
        const bf16* Vs = VsB[kt & 1];

        float c[8][4];
        computeS(c, kt, Ks);

        unsigned pr[8][2];
        #pragma unroll
        for (int nf = 0; nf < 8; nf++) {
            bf162 v0, v1;
            v0.x = __float2bfloat16(__expf(c[nf][0] - mA) * invA);
            v0.y = __float2bfloat16(__expf(c[nf][1] - mA) * invA);
            v1.x = __float2bfloat16(__expf(c[nf][2] - mB) * invB);
            v1.y = __float2bfloat16(__expf(c[nf][3] - mB) * invB);
            pr[nf][0] = *reinterpret_cast<unsigned*>(&v0);
            pr[nf][1] = *reinterpret_cast<unsigned*>(&v1);
        }

        float d[16][4];
        #pragma unroll
        for (int nb = 0; nb < 16; nb++)
            #pragma unroll
            for (int e = 0; e < 4; e++) d[nb][e] = 0.f;

        #pragma unroll
        for (int kb = 0; kb < 4; kb++) {
            unsigned a[4] = {pr[2*kb][0], pr[2*kb][1], pr[2*kb+1][0], pr[2*kb+1][1]};
            unsigned bv[16][2];
            #pragma unroll
            for (int nbp = 0; nbp < 8; nbp++) {
                unsigned r0, r1, r2, r3;
                ldmBT(r0, r1, r2, r3,
                      saddr(Vs + (kb * 16 + (lane & 15)) * FLD + nbp * 16 + (lane >> 4) * 8));
                bv[nbp*2][0]   = r0; bv[nbp*2][1]   = r1;
                bv[nbp*2+1][0] = r2; bv[nbp*2+1][1] = r3;
            }
            #pragma unroll
            for (int nb = 0; nb < 16; nb++)
                mma16816bf(d[nb], a, bv[nb]);
        }
        #pragma unroll
        for (int nb = 0; nb < 16; nb++)
            #pragma unroll
            for (int e = 0; e < 4; e++) o[nb][e] += d[nb][e];
    }

    const int b = bh >> 4, h = bh & 15;
    #pragma unroll
    for (int nb = 0; nb < 16; nb++) {
        const int col = nb * 8 + lc;
        __half2 vA, vB;
        vA.x = __float2half(__bfloat162float(__float2bfloat16(o[nb][0])));
        vA.y = __float2half(__bfloat162float(__float2bfloat16(o[nb][1])));
        vB.x = __float2half(__bfloat162float(__float2bfloat16(o[nb][2])));
        vB.y = __float2half(__bfloat162float(__float2bfloat16(o[nb][3])));
        *reinterpret_cast<__half2*>(
            g_attnb + ((size_t)(b * Sn + rA)) * Dn + h * DHn + col) = vA;
        *reinterpret_cast<__half2*>(
            g_attnb + ((size_t)(b * Sn + rB)) * Dn + h * DHn + col) = vB;
    }
}

// ============================================================
extern "C" void kernel_launch(void* const* d_in, const int* in_sizes, int n_in,
                              void* d_out, int out_size)
{
    const float* x  = (const float*)d_in[0];
    const float* w[4] = {(const float*)d_in[1], (const float*)d_in[2],
                         (const float*)d_in[3], (const float*)d_in[4]};
    float* out = (float*)d_out;

    __half *xhi, *xlo, *whiB, *wloB, *attnb;
    cudaGetSymbolAddress((void**)&xhi, g_xhi);
    cudaGetSymbolAddress((void**)&xlo, g_xlo);
    cudaGetSymbolAddress((void**)&attnb, g_attnb);
    cudaGetSymbolAddress((void**)&whiB, g_whi);
    cudaGetSymbolAddress((void**)&wloB, g_wlo);

    cudaFuncSetAttribute(gemm_mma<0>, cudaFuncAttributeMaxDynamicSharedMemorySize, SMEM_BYTES);
    cudaFuncSetAttribute(gemm_mma<1>, cudaFuncAttributeMaxDynamicSharedMemorySize, SMEM_BYTES);
    cudaFuncSetAttribute(flash_tc, cudaFuncAttributeMaxDynamicSharedMemorySize, FLASH_SMEM);

    const int n4 = Mn * Dn / 4;
    const int m4 = Dn * Dn / 4;

    rope_tab_kernel<<<(Sn * 64 + 255) / 256, 256>>>();                 // 0
    split_kernel<<<(n4 + 255) / 256, 256>>>(x, xhi, xlo, n4);          // 1
    wsplit_all<<<dim3(m4 / 256, 4), 256>>>(w[0], w[1], w[2], w[3],     // 2
                                           whiB, wloB);

    // 3: fused QKV projection (rope + bf16 epilogues)
    gemm_mma<0><<<dim3(48, Mn / 128), 512, SMEM_BYTES>>>(xhi, xlo, whiB, wloB, nullptr);

    // 4: flash attention (double-buffered)
    flash_tc<<<dim3(Sn / 64, Bn * Hn), 128, FLASH_SMEM>>>();

    // 5: out = attnb @ wo (2 phases)
    gemm_mma<1><<<dim3(16, Mn / 128), 512, SMEM_BYTES>>>(
        attnb, nullptr, whiB + (size_t)3 * Dn * Dn, wloB + (size_t)3 * Dn * Dn, out);
}

// round 15
// speedup vs baseline: 1.0615x; 1.0566x over previous
#include <cuda_runtime.h>
#include <cuda_bf16.h>
#include <cuda_fp16.h>
#include <math.h>
#include <stdint.h>

// Problem dims
#define Bn  2
#define Sn  2048
#define Dn  2048
#define Hn  16
#define DHn 128
#define Mn  (Bn*Sn)   // 4096

typedef __nv_bfloat16 bf16;
typedef __nv_bfloat162 bf162;

// ---------------- scratch (device globals; no allocation allowed) ----------
__device__ __half g_xhi[(size_t)Mn*Dn];
__device__ __half g_xlo[(size_t)Mn*Dn];
__device__ __half g_whi[4][(size_t)Dn*Dn];   // wq, wk, wv, wo  [K,N]
__device__ __half g_wlo[4][(size_t)Dn*Dn];
__device__ bf16 g_Q[(size_t)Bn*Hn*Sn*DHn];   // [b,h,s,dh]
__device__ bf16 g_K[(size_t)Bn*Hn*Sn*DHn];
__device__ bf16 g_V[(size_t)Bn*Hn*Sn*DHn];
__device__ __half g_attnb[(size_t)Mn*Dn];    // [b,s,d] fp16 (exact bf16 values)
__device__ float2 g_rope[(size_t)Sn*64];     // (cos, sin)

__device__ __forceinline__ unsigned saddr(const void* p) {
    return (unsigned)__cvta_generic_to_shared(p);
}

// ---------------- cp.async helpers -----------------------------------------
__device__ __forceinline__ void cpa16(unsigned s, const void* g) {
    asm volatile("cp.async.cg.shared.global [%0], [%1], 16;\n" :: "r"(s), "l"(g));
}
__device__ __forceinline__ void cpcommit() {
    asm volatile("cp.async.commit_group;\n" ::);
}
template<int NW> __device__ __forceinline__ void cpwait() {
    asm volatile("cp.async.wait_group %0;\n" :: "n"(NW));
}

// ---------------- helpers ---------------------------------------------------
__global__ void split_kernel(const float* __restrict__ s,
                             __half* __restrict__ hi, __half* __restrict__ lo, int n4)
{
    int i = blockIdx.x * blockDim.x + threadIdx.x;
    if (i >= n4) return;
    float4 v = reinterpret_cast<const float4*>(s)[i];
    __half h0 = __float2half(v.x), h1 = __float2half(v.y);
    __half h2 = __float2half(v.z), h3 = __float2half(v.w);
    __half2 H0; H0.x = h0; H0.y = h1;
    __half2 H1; H1.x = h2; H1.y = h3;
    reinterpret_cast<__half2*>(hi)[2*i]   = H0;
    reinterpret_cast<__half2*>(hi)[2*i+1] = H1;
    __half2 L0, L1;
    L0.x = __float2half(v.x - __half2float(h0));
    L0.y = __float2half(v.y - __half2float(h1));
    L1.x = __float2half(v.z - __half2float(h2));
    L1.y = __float2half(v.w - __half2float(h3));
    reinterpret_cast<__half2*>(lo)[2*i]   = L0;
    reinterpret_cast<__half2*>(lo)[2*i+1] = L1;
}

// fused 4-weight split: blockIdx.y selects the weight matrix
__global__ void wsplit_all(const float* __restrict__ w0, const float* __restrict__ w1,
                           const float* __restrict__ w2, const float* __restrict__ w3,
                           __half* __restrict__ hiB, __half* __restrict__ loB)
{
    const int which = blockIdx.y;
    const float* s = (which == 0) ? w0 : (which == 1) ? w1 : (which == 2) ? w2 : w3;
    __half* hi = hiB + (size_t)which * Dn * Dn;
    __half* lo = loB + (size_t)which * Dn * Dn;
    int i = blockIdx.x * blockDim.x + threadIdx.x;
    float4 v = reinterpret_cast<const float4*>(s)[i];
    __half h0 = __float2half(v.x), h1 = __float2half(v.y);
    __half h2 = __float2half(v.z), h3 = __float2half(v.w);
    __half2 H0; H0.x = h0; H0.y = h1;
    __half2 H1; H1.x = h2; H1.y = h3;
    reinterpret_cast<__half2*>(hi)[2*i]   = H0;
    reinterpret_cast<__half2*>(hi)[2*i+1] = H1;
    __half2 L0, L1;
    L0.x = __float2half(v.x - __half2float(h0));
    L0.y = __float2half(v.y - __half2float(h1));
    L1.x = __float2half(v.z - __half2float(h2));
    L1.y = __float2half(v.w - __half2float(h3));
    reinterpret_cast<__half2*>(lo)[2*i]   = L0;
    reinterpret_cast<__half2*>(lo)[2*i+1] = L1;
}

__global__ void rope_tab_kernel()
{
    int idx = blockIdx.x * blockDim.x + threadIdx.x;   // s*64 + i
    if (idx >= Sn * 64) return;
    int s = idx >> 6, i = idx & 63;
    const float LOG1E4 = 9.210340371976184f;
    float inv = expf(-((float)(2 * i) / 128.0f) * LOG1E4);
    float ang = (float)s * inv;
    float sn, cs;
    sincosf(ang, &sn, &cs);
    g_rope[idx] = make_float2(cs, sn);
}

// ---------------- mma primitives -------------------------------------------
__device__ __forceinline__ void ldmA(unsigned &r0, unsigned &r1, unsigned &r2, unsigned &r3, unsigned a) {
    asm volatile("ldmatrix.sync.aligned.m8n8.x4.shared.b16 {%0,%1,%2,%3}, [%4];"
                 : "=r"(r0), "=r"(r1), "=r"(r2), "=r"(r3) : "r"(a));
}
__device__ __forceinline__ void ldmBT(unsigned &r0, unsigned &r1, unsigned &r2, unsigned &r3, unsigned a) {
    asm volatile("ldmatrix.sync.aligned.m8n8.x4.trans.shared.b16 {%0,%1,%2,%3}, [%4];"
                 : "=r"(r0), "=r"(r1), "=r"(r2), "=r"(r3) : "r"(a));
}
__device__ __forceinline__ void mma16816(float* d, const unsigned* a, const unsigned* b) {
    asm volatile("mma.sync.aligned.m16n8k16.row.col.f32.f16.f16.f32 "
                 "{%0,%1,%2,%3}, {%4,%5,%6,%7}, {%8,%9}, {%0,%1,%2,%3};"
                 : "+f"(d[0]), "+f"(d[1]), "+f"(d[2]), "+f"(d[3])
                 : "r"(a[0]), "r"(a[1]), "r"(a[2]), "r"(a[3]), "r"(b[0]), "r"(b[1]));
}
__device__ __forceinline__ void mma16816bf(float* d, const unsigned* a, const unsigned* b) {
    asm volatile("mma.sync.aligned.m16n8k16.row.col.f32.bf16.bf16.f32 "
                 "{%0,%1,%2,%3}, {%4,%5,%6,%7}, {%8,%9}, {%0,%1,%2,%3};"
                 : "+f"(d[0]), "+f"(d[1]), "+f"(d[2]), "+f"(d[3])
                 : "r"(a[0]), "r"(a[1]), "r"(a[2]), "r"(a[3]), "r"(b[0]), "r"(b[1]));
}

// ---------------- fp16 tensor-core GEMM: R12 warp config, k64/iteration -----
// 512 thr, 16 warps (4x4), 32x32 warp tiles, block 128x128, k-tile 64,
// 3-stage cp.async, 1 sync per k64. fp32 drain every 2 iters (chain 8 —
// accumulation order bit-identical to the k32/drain-4 config).
constexpr int LDA = 72, LDB = 136;
constexpr int A_STG = 128 * LDA;     // 128 x 64 A tile (padded)
constexpr int B_STG = 64 * LDB;      // 64 x 128 B tile (padded)
constexpr int NSTG  = 3;
constexpr int SMEM_BYTES = NSTG * (A_STG + B_STG) * 2;   // 107,520

template<int KIND>
__global__ void __launch_bounds__(512)
gemm_mma(const __half* __restrict__ a_hi, const __half* __restrict__ a_lo,
         const __half* __restrict__ w_hi, const __half* __restrict__ w_lo,
         float* __restrict__ outF)
{
    constexpr int K = Dn, N = Dn;
    extern __shared__ __half smem[];
    __half* AsBase = smem;
    __half* BsBase = smem + NSTG * A_STG;

    const int tid = threadIdx.x;
    const int wid = tid >> 5, lane = tid & 31;
    const int wm = wid & 3, wn = wid >> 2;       // 4 x 4 warps, 32x32 tiles
    const int m0 = blockIdx.y * 128;

    int mode, n0, nPhase;
    const __half *APh[3], *BPh[3];
    if (KIND == 0) {
        const int which = blockIdx.x >> 4;
        mode = which;
        n0 = (blockIdx.x & 15) * 128;
        const __half* W1 = w_hi + (size_t)which * Dn * Dn;
        const __half* W2 = w_lo + (size_t)which * Dn * Dn;
        APh[0] = a_hi; APh[1] = a_lo; APh[2] = a_hi;
        BPh[0] = W1;   BPh[1] = W1;   BPh[2] = W2;
        nPhase = 3;
    } else {
        mode = 3;
        n0 = blockIdx.x * 128;
        APh[0] = a_hi; APh[1] = a_hi; APh[2] = a_hi;
        BPh[0] = w_hi; BPh[1] = w_lo; BPh[2] = w_lo;
        nPhase = 2;
    }
    const int nIter = nPhase * (K / 64);   // phase = i>>5, ktile = i&31

    float d[2][4][4];
    float sum[2][4][4];
    #pragma unroll
    for (int mf = 0; mf < 2; mf++)
        #pragma unroll
        for (int nf = 0; nf < 4; nf++)
            #pragma unroll
            for (int e = 0; e < 4; e++) { d[mf][nf][e] = 0.f; sum[mf][nf][e] = 0.f; }

    // loading layout (512 threads): A row tid>>2, 16-half chunk (tid&3)*16;
    // B row tid>>3, 16-half chunk (tid&7)*16. Two cp.async each per iter.
    const int arow = tid >> 2, acol = (tid & 3) * 16;
    const int brow = tid >> 3, bcol = (tid & 7) * 16;

    unsigned sA[NSTG], sB[NSTG];
    #pragma unroll
    for (int b = 0; b < NSTG; b++) {
        sA[b] = saddr(AsBase + b * A_STG + arow * LDA + acol);
        sB[b] = saddr(BsBase + b * B_STG + brow * LDB + bcol);
    }

    auto issue = [&](int i) {
        const int ph = i >> 5;
        const int kt = (i & 31) * 64;
        const __half* ga = APh[ph] + (size_t)(m0 + arow) * K + acol + kt;
        const __half* gb = BPh[ph] + (size_t)(kt + brow) * N + n0 + bcol;
        const int b = i % 3;
        cpa16(sA[b],      ga);
        cpa16(sA[b] + 16, ga + 8);
        cpa16(sB[b],      gb);
        cpa16(sB[b] + 16, gb + 8);
        cpcommit();
    };

    issue(0);
    issue(1);

    for (int i = 0; i < nIter; i++) {
        if (i + 1 < nIter) cpwait<1>(); else cpwait<0>();
        __syncthreads();
        if (i + 2 < nIter) issue(i + 2);

        const int stg = i % 3;
        const __half* as = AsBase + stg * A_STG;
        const __half* bs = BsBase + stg * B_STG;

        #pragma unroll
        for (int kk = 0; kk < 64; kk += 16) {
            unsigned a[2][4];
            #pragma unroll
            for (int mf = 0; mf < 2; mf++) {
                const __half* p = as + (wm * 32 + mf * 16 + (lane & 15)) * LDA
                                     + kk + (lane >> 4) * 8;
                ldmA(a[mf][0], a[mf][1], a[mf][2], a[mf][3], saddr(p));
            }
            unsigned bfr[4][2];
            #pragma unroll
            for (int nq = 0; nq < 2; nq++) {
                const __half* p = bs + (kk + (lane & 15)) * LDB
                                     + wn * 32 + nq * 16 + (lane >> 4) * 8;
                unsigned r0, r1, r2, r3;
                ldmBT(r0, r1, r2, r3, saddr(p));
                bfr[nq*2][0] = r0; bfr[nq*2][1] = r1;
                bfr[nq*2+1][0] = r2; bfr[nq*2+1][1] = r3;
            }
            #pragma unroll
            for (int mf = 0; mf < 2; mf++)
                #pragma unroll
                for (int nf = 0; nf < 4; nf++)
                    mma16816(d[mf][nf], a[mf], bfr[nf]);
        }

        // drain every 2 k64-iters (HMMA chain length 8 — bit-identical order)
        if ((i & 1) == 1) {
            #pragma unroll
            for (int mf = 0; mf < 2; mf++)
                #pragma unroll
                for (int nf = 0; nf < 4; nf++)
                    #pragma unroll
                    for (int e = 0; e < 4; e++) {
                        sum[mf][nf][e] += d[mf][nf][e];
                        d[mf][nf][e] = 0.f;
                    }
        }
    }

    const int lr = lane >> 2;
    const int lc = (lane & 3) * 2;
    #pragma unroll
    for (int mf = 0; mf < 2; mf++) {
        #pragma unroll
        for (int nf = 0; nf < 4; nf++) {
            float* dd = sum[mf][nf];
            const int row0 = m0 + wm * 32 + mf * 16 + lr;
            const int col  = n0 + wn * 32 + nf * 8 + lc;
            #pragma unroll
            for (int half = 0; half < 2; half++) {
                const int row = row0 + half * 8;
                const float e = dd[half*2], o = dd[half*2 + 1];
                if (KIND == 1) {
                    *reinterpret_cast<float2*>(outF + (size_t)row * N + col) =
                        make_float2(e, o);
                } else {
                    const int b = row >> 11, s = row & (Sn - 1);
                    const int h = col >> 7, jd = col & (DHn - 1);
                    bf16* dst = (mode == 0) ? g_Q : (mode == 1) ? g_K : g_V;
                    bf162 val;
                    if (mode == 2) {
                        val.x = __float2bfloat16(e);
                        val.y = __float2bfloat16(o);
                    } else {
                        float2 cssn = g_rope[s * 64 + (jd >> 1)];
                        val.x = __float2bfloat16(e * cssn.x - o * cssn.y);
                        val.y = __float2bfloat16(e * cssn.y + o * cssn.x);
                    }
                    *reinterpret_cast<bf162*>(
                        dst + ((size_t)(b * Hn + h) * Sn + s) * DHn + jd) = val;
                }
            }
        }
    }
}

// ============================================================
// Tensor-core two-pass causal flash attention (exact R8 config:
// 64 q-rows/CTA, 4 warps, 128 threads, single-buffered tiles).
// ============================================================
constexpr int FLD = 136;
constexpr int FTILE = 64 * FLD;
constexpr int FLASH_SMEM = 3 * FTILE * 2;   // 52,224

__global__ void __launch_bounds__(128)
flash_tc()
{
    extern __shared__ bf16 fs[];
    bf16* Qs = fs;
    bf16* Ks = fs + FTILE;
    bf16* Vs = fs + 2 * FTILE;

    const int tid  = threadIdx.x;
    const int warp = tid >> 5, lane = tid & 31;
    const int bh   = blockIdx.y;
    const int q0   = blockIdx.x * 64;
    const int nT   = blockIdx.x + 1;
    const float scale = 0.08838834764831845f;

    const bf16* Qg = g_Q + ((size_t)bh * Sn + q0) * DHn;
    const bf16* Kg = g_K + (size_t)bh * Sn * DHn;
    const bf16* Vg = g_V + (size_t)bh * Sn * DHn;

    const int lrow = tid & 63;
    const int lcb  = (tid >> 6) << 6;

    auto load_tile = [&](const bf16* g, bf16* s) {
        const bf16* gp = g + (size_t)lrow * DHn + lcb;
        unsigned sp = saddr(s + lrow * FLD + lcb);
        #pragma unroll
        for (int i = 0; i < 8; i++) cpa16(sp + i * 16, gp + i * 8);
    };

    load_tile(Qg, Qs);
    cpcommit();

    const int lr = lane >> 2;
    const int lc = (lane & 3) * 2;
    const int rA = q0 + warp * 16 + lr;
    const int rB = rA + 8;

    auto computeS = [&](float c[8][4], int kt) {
        #pragma unroll
        for (int nf = 0; nf < 8; nf++)
            #pragma unroll
            for (int e = 0; e < 4; e++) c[nf][e] = 0.f;
        #pragma unroll
        for (int ks = 0; ks < 8; ks++) {
            unsigned a[4];
            ldmA(a[0], a[1], a[2], a[3],
                 saddr(Qs + (warp * 16 + (lane & 15)) * FLD + ks * 16 + (lane >> 4) * 8));
            unsigned bk[8][2];
            #pragma unroll
            for (int nq = 0; nq < 4; nq++) {
                unsigned r0, r1, r2, r3;
                ldmA(r0, r1, r2, r3,
                     saddr(Ks + (nq * 16 + (lane & 15)) * FLD + ks * 16 + (lane >> 4) * 8));
                bk[nq*2][0]   = r0; bk[nq*2][1]   = r2;
                bk[nq*2+1][0] = r1; bk[nq*2+1][1] = r3;
            }
            #pragma unroll
            for (int nf = 0; nf < 8; nf++)
                mma16816bf(c[nf], a, bk[nf]);
        }
        if (kt == nT - 1) {
            #pragma unroll
            for (int nf = 0; nf < 8; nf++) {
                const int col = kt * 64 + nf * 8 + lc;
                c[nf][0] = (col     <= rA) ? c[nf][0] * scale : -INFINITY;
                c[nf][1] = (col + 1 <= rA) ? c[nf][1] * scale : -INFINITY;
                c[nf][2] = (col     <= rB) ? c[nf][2] * scale : -INFINITY;
                c[nf][3] = (col + 1 <= rB) ? c[nf][3] * scale : -INFINITY;
            }
        } else {
            #pragma unroll
            for (int nf = 0; nf < 8; nf++)
                #pragma unroll
                for (int e = 0; e < 4; e++) c[nf][e] *= scale;
        }
    };

    float mA = -INFINITY, lA = 0.f, mB = -INFINITY, lB = 0.f;
    for (int kt = 0; kt < nT; kt++) {
        __syncthreads();
        load_tile(Kg + (size_t)kt * 64 * DHn, Ks);
        cpcommit();
        cpwait<0>();
        __syncthreads();

        float c[8][4];
        computeS(c, kt);

        float tA = -INFINITY, tB = -INFINITY;
        #pragma unroll
        for (int nf = 0; nf < 8; nf++) {
            tA = fmaxf(tA, fmaxf(c[nf][0], c[nf][1]));
            tB = fmaxf(tB, fmaxf(c[nf][2], c[nf][3]));
        }
        tA = fmaxf(tA, __shfl_xor_sync(0xffffffffu, tA, 1));
        tA = fmaxf(tA, __shfl_xor_sync(0xffffffffu, tA, 2));
        tB = fmaxf(tB, __shfl_xor_sync(0xffffffffu, tB, 1));
        tB = fmaxf(tB, __shfl_xor_sync(0xffffffffu, tB, 2));

        const float mnA = fmaxf(mA, tA), mnB = fmaxf(mB, tB);
        float sA = 0.f, sB = 0.f;
        #pragma unroll
        for (int nf = 0; nf < 8; nf++) {
            sA += __expf(c[nf][0] - mnA) + __expf(c[nf][1] - mnA);
            sB += __expf(c[nf][2] - mnB) + __expf(c[nf][3] - mnB);
        }
        sA += __shfl_xor_sync(0xffffffffu, sA, 1);
        sA += __shfl_xor_sync(0xffffffffu, sA, 2);
        sB += __shfl_xor_sync(0xffffffffu, sB, 1);
        sB += __shfl_xor_sync(0xffffffffu, sB, 2);

        lA = lA * __expf(mA - mnA) + sA; mA = mnA;
        lB = lB * __expf(mB - mnB) + sB; mB = mnB;
    }
    const float invA = 1.0f / lA, invB = 1.0f / lB;

    float o[16][4];
    #pragma unroll
    for (int nb = 0; nb < 16; nb++)
        #pragma unroll
        for (int e = 0; e < 4; e++) o[nb][e] = 0.f;

    for (int kt = 0; kt < nT; kt++) {
        __syncthreads();
        load_tile(Kg + (size_t)kt * 64 * DHn, Ks);
        load_tile(Vg + (size_t)kt * 64 * DHn, Vs);
        cpcommit();
        cpwait<0>();
        __syncthreads();

        float c[8][4];
        computeS(c, kt);

        unsigned pr[8][2];
        #pragma unroll
        for (int nf = 0; nf < 8; nf++) {
            bf162 v0, v1;
            v0.x = __float2bfloat16(__expf(c[nf][0] - mA) * invA);
            v0.y = __float2bfloat16(__expf(c[nf][1] - mA) * invA);
            v1.x = __float2bfloat16(__expf(c[nf][2] - mB) * invB);
            v1.y = __float2bfloat16(__expf(c[nf][3] - mB) * invB);
            pr[nf][0] = *reinterpret_cast<unsigned*>(&v0);
            pr[nf][1] = *reinterpret_cast<unsigned*>(&v1);
        }

        float d[16][4];
        #pragma unroll
        for (int nb = 0; nb < 16; nb++)
            #pragma unroll
            for (int e = 0; e < 4; e++) d[nb][e] = 0.f;

        #pragma unroll
        for (int kb = 0; kb < 4; kb++) {
            unsigned a[4] = {pr[2*kb][0], pr[2*kb][1], pr[2*kb+1][0], pr[2*kb+1][1]};
            unsigned bv[16][2];
            #pragma unroll
            for (int nbp = 0; nbp < 8; nbp++) {
                unsigned r0, r1, r2, r3;
                ldmBT(r0, r1, r2, r3,
                      saddr(Vs + (kb * 16 + (lane & 15)) * FLD + nbp * 16 + (lane >> 4) * 8));
                bv[nbp*2][0]   = r0; bv[nbp*2][1]   = r1;
                bv[nbp*2+1][0] = r2; bv[nbp*2+1][1] = r3;
            }
            #pragma unroll
            for (int nb = 0; nb < 16; nb++)
                mma16816bf(d[nb], a, bv[nb]);
        }
        #pragma unroll
        for (int nb = 0; nb < 16; nb++)
            #pragma unroll
            for (int e = 0; e < 4; e++) o[nb][e] += d[nb][e];
    }

    const int b = bh >> 4, h = bh & 15;
    #pragma unroll
    for (int nb = 0; nb < 16; nb++) {
        const int col = nb * 8 + lc;
        __half2 vA, vB;
        vA.x = __float2half(__bfloat162float(__float2bfloat16(o[nb][0])));
        vA.y = __float2half(__bfloat162float(__float2bfloat16(o[nb][1])));
        vB.x = __float2half(__bfloat162float(__float2bfloat16(o[nb][2])));
        vB.y = __float2half(__bfloat162float(__float2bfloat16(o[nb][3])));
        *reinterpret_cast<__half2*>(
            g_attnb + ((size_t)(b * Sn + rA)) * Dn + h * DHn + col) = vA;
        *reinterpret_cast<__half2*>(
            g_attnb + ((size_t)(b * Sn + rB)) * Dn + h * DHn + col) = vB;
    }
}

// ============================================================
extern "C" void kernel_launch(void* const* d_in, const int* in_sizes, int n_in,
                              void* d_out, int out_size)
{
    const float* x  = (const float*)d_in[0];
    const float* w[4] = {(const float*)d_in[1], (const float*)d_in[2],
                         (const float*)d_in[3], (const float*)d_in[4]};
    float* out = (float*)d_out;

    __half *xhi, *xlo, *whiB, *wloB, *attnb;
    cudaGetSymbolAddress((void**)&xhi, g_xhi);
    cudaGetSymbolAddress((void**)&xlo, g_xlo);
    cudaGetSymbolAddress((void**)&attnb, g_attnb);
    cudaGetSymbolAddress((void**)&whiB, g_whi);
    cudaGetSymbolAddress((void**)&wloB, g_wlo);

    cudaFuncSetAttribute(gemm_mma<0>, cudaFuncAttributeMaxDynamicSharedMemorySize, SMEM_BYTES);
    cudaFuncSetAttribute(gemm_mma<1>, cudaFuncAttributeMaxDynamicSharedMemorySize, SMEM_BYTES);
    cudaFuncSetAttribute(flash_tc, cudaFuncAttributeMaxDynamicSharedMemorySize, FLASH_SMEM);

    const int n4 = Mn * Dn / 4;
    const int m4 = Dn * Dn / 4;

    rope_tab_kernel<<<(Sn * 64 + 255) / 256, 256>>>();                 // 0
    split_kernel<<<(n4 + 255) / 256, 256>>>(x, xhi, xlo, n4);          // 1
    wsplit_all<<<dim3(m4 / 256, 4), 256>>>(w[0], w[1], w[2], w[3],     // 2
                                           whiB, wloB);

    // 3: fused QKV projection (rope + bf16 epilogues)
    gemm_mma<0><<<dim3(48, Mn / 128), 512, SMEM_BYTES>>>(xhi, xlo, whiB, wloB, nullptr);

    // 4: flash attention
    flash_tc<<<dim3(Sn / 64, Bn * Hn), 128, FLASH_SMEM>>>();

    // 5: out = attnb @ wo (2 phases)
    gemm_mma<1><<<dim3(16, Mn / 128), 512, SMEM_BYTES>>>(
        attnb, nullptr, whiB + (size_t)3 * Dn * Dn, wloB + (size_t)3 * Dn * Dn, out);
}